// round 2
// baseline (speedup 1.0000x reference)
#include <cuda_runtime.h>
#include <math.h>

#define Hn   2048
#define SEQ  2048
#define NBLK 148
#define TPB  256
#define CPT  8      // Hn / TPB columns per thread
#define MAXR 14     // max rows per block: ceil(2048/148)

// ------------------------------------------------------------------
// Static device scratch (no cudaMalloc allowed)
// ------------------------------------------------------------------
__device__ float d_XF[SEQ * Hn];   // x @ Wfx^T + bfx
__device__ float d_XH[SEQ * Hn];   // x @ Whx^T + bhx
__device__ float d_hbuf[Hn];       // current hidden state (global, cross-block)
__device__ float d_gbuf[Hn];       // f * h (global, cross-block)
__device__ unsigned d_flags[256];  // per-block barrier generation (zero-init)

// ------------------------------------------------------------------
// Distributed grid barrier: each block release-stores its OWN flag
// (no contention), warp 0 polls all 148 flags with acquire loads.
// Generations are monotonically increasing across graph replays;
// wrap-safe signed compare. All 148 blocks co-resident (1/SM).
// ------------------------------------------------------------------
__device__ __forceinline__ void gbar(unsigned gen) {
    __syncthreads();                     // order all threads' prior writes
    const int tid = threadIdx.x;
    if (tid == 0) {
        asm volatile("st.release.gpu.global.u32 [%0], %1;"
                     :: "l"(&d_flags[blockIdx.x]), "r"(gen) : "memory");
    }
    if (tid < 32) {
        bool done = false;
        do {
            bool ok = true;
#pragma unroll
            for (int k = 0; k < 5; k++) {
                int idx = tid + (k << 5);
                if (idx < NBLK) {
                    unsigned v;
                    asm volatile("ld.acquire.gpu.global.u32 %0, [%1];"
                                 : "=r"(v) : "l"(&d_flags[idx]) : "memory");
                    ok &= ((int)(v - gen) >= 0);
                }
            }
            done = __all_sync(0xffffffffu, ok);
        } while (!done);
    }
    __syncthreads();
}

// ------------------------------------------------------------------
// Precompute GEMM:  C[s][n] = sum_k x[s][k] * W[n][k] + bias[n]
// blockIdx.z selects (Wfx,bfx)->d_XF or (Whx,bhx)->d_XH.
// 128x128 tile, BK=16, 8x8 per thread, 256 threads.
// ------------------------------------------------------------------
__global__ __launch_bounds__(256, 2) void mgu_gemm(
    const float* __restrict__ x,
    const float* __restrict__ Wfx, const float* __restrict__ bfx,
    const float* __restrict__ Whx, const float* __restrict__ bhx)
{
    const float* __restrict__ W    = (blockIdx.z == 0) ? Wfx : Whx;
    const float* __restrict__ bias = (blockIdx.z == 0) ? bfx : bhx;
    float* __restrict__ C          = (blockIdx.z == 0) ? d_XF : d_XH;

    __shared__ float As[16][132];
    __shared__ float Bs[16][132];

    const int bm  = blockIdx.y * 128;   // rows of x (s)
    const int bn  = blockIdx.x * 128;   // rows of W (output h)
    const int tid = threadIdx.x;
    const int tr  = (tid >> 4) << 3;    // 0..120 step 8
    const int tc  = (tid & 15) << 3;

    float acc[8][8];
#pragma unroll
    for (int i = 0; i < 8; i++)
#pragma unroll
        for (int j = 0; j < 8; j++) acc[i][j] = 0.f;

    for (int k0 = 0; k0 < 2048; k0 += 16) {
#pragma unroll
        for (int i = 0; i < 2; i++) {
            int q   = tid + (i << 8);        // 0..511
            int row = q >> 2;                // 0..127
            int kq  = (q & 3) << 2;          // 0,4,8,12
            float4 va = *(const float4 *)(x + (size_t)(bm + row) * 2048 + k0 + kq);
            As[kq + 0][row] = va.x; As[kq + 1][row] = va.y;
            As[kq + 2][row] = va.z; As[kq + 3][row] = va.w;
            float4 vb = *(const float4 *)(W + (size_t)(bn + row) * 2048 + k0 + kq);
            Bs[kq + 0][row] = vb.x; Bs[kq + 1][row] = vb.y;
            Bs[kq + 2][row] = vb.z; Bs[kq + 3][row] = vb.w;
        }
        __syncthreads();
#pragma unroll
        for (int k = 0; k < 16; k++) {
            float a[8], b[8];
            *(float4 *)(a)     = *(const float4 *)&As[k][tr];
            *(float4 *)(a + 4) = *(const float4 *)&As[k][tr + 4];
            *(float4 *)(b)     = *(const float4 *)&Bs[k][tc];
            *(float4 *)(b + 4) = *(const float4 *)&Bs[k][tc + 4];
#pragma unroll
            for (int i = 0; i < 8; i++)
#pragma unroll
                for (int j = 0; j < 8; j++) acc[i][j] += a[i] * b[j];
        }
        __syncthreads();
    }

    float bj[8];
#pragma unroll
    for (int j = 0; j < 8; j++) bj[j] = __ldg(&bias[bn + tc + j]);
#pragma unroll
    for (int i = 0; i < 8; i++) {
        float4 v0 = make_float4(acc[i][0] + bj[0], acc[i][1] + bj[1],
                                acc[i][2] + bj[2], acc[i][3] + bj[3]);
        float4 v1 = make_float4(acc[i][4] + bj[4], acc[i][5] + bj[5],
                                acc[i][6] + bj[6], acc[i][7] + bj[7]);
        size_t off = (size_t)(bm + tr + i) * 2048 + bn + tc;
        *(float4 *)(C + off)     = v0;
        *(float4 *)(C + off + 4) = v1;
    }
}

// ------------------------------------------------------------------
// Persistent scan kernel. Block b owns rows [r0,r1) of BOTH Wfh and
// Whf, cached in SMEM (<= 14 rows * 2 * 8KB = 224KB).
// Per step: phase A -> f, g = f*h published via L2; gbar;
//           phase B -> h_new published; gbar.
// Cross-block vectors read with __ldcg (bypass stale L1).
// ------------------------------------------------------------------
__global__ __launch_bounds__(TPB, 1) void mgu_scan(
    const float* __restrict__ h0,
    const float* __restrict__ Wfh, const float* __restrict__ bfh,
    const float* __restrict__ Whf, const float* __restrict__ bhf,
    float* __restrict__ out)
{
    extern __shared__ float sW[];
    __shared__ float sPart[MAXR][8];
    __shared__ float sF[MAXR];
    __shared__ float sHold[MAXR];
    __shared__ float sBfh[MAXR];
    __shared__ float sBhf[MAXR];

    const int b   = blockIdx.x;
    const int tid = threadIdx.x;
    const int r0  = (b * Hn) / NBLK;
    const int r1  = ((b + 1) * Hn) / NBLK;
    const int nr  = r1 - r0;               // 13 or 14

    float* sWf = sW;                        // Wfh rows
    float* sWh = sW + nr * Hn;              // Whf rows

    // load weight rows into SMEM (coalesced float4)
    {
        const float4* gf = (const float4 *)(Wfh + (size_t)r0 * Hn);
        const float4* gh = (const float4 *)(Whf + (size_t)r0 * Hn);
        float4* sf4 = (float4 *)sWf;
        float4* sh4 = (float4 *)sWh;
        const int n4 = nr * (Hn / 4);
        for (int i = tid; i < n4; i += TPB) { sf4[i] = gf[i]; sh4[i] = gh[i]; }
    }
    if (tid < nr) { sBfh[tid] = bfh[r0 + tid]; sBhf[tid] = bhf[r0 + tid]; }

    // init global hidden state
    for (int i = b * TPB + tid; i < Hn; i += NBLK * TPB) d_hbuf[i] = h0[i];

    // barrier generation base: my own flag value from the previous run
    // (flags are monotonic; only this block ever writes d_flags[b])
    unsigned gen = __ldcg(&d_flags[b]);
    gen += 1;
    gbar(gen);

    const int c0   = tid * CPT;
    const int wid  = tid >> 5;
    const int lane = tid & 31;

    for (int t = 0; t < SEQ; t++) {
        // ============ phase A : f = sigmoid(xf + Wfh h + bfh), g = f*h ======
        float xf_v = 0.f, h_own = 0.f;
        if (tid < nr) {
            xf_v  = __ldg(&d_XF[(size_t)t * Hn + r0 + tid]);
            h_own = __ldcg(&d_hbuf[r0 + tid]);
        }
        float4 hv0 = __ldcg((const float4 *)&d_hbuf[c0]);
        float4 hv1 = __ldcg((const float4 *)&d_hbuf[c0 + 4]);

        float acc[MAXR];
#pragma unroll
        for (int r = 0; r < MAXR; r++) acc[r] = 0.f;
#pragma unroll
        for (int r = 0; r < MAXR; r++) {
            if (r < nr) {
                const float4* wp = (const float4 *)(sWf + r * Hn + c0);
                float4 w0 = wp[0], w1 = wp[1];
                acc[r] = w0.x * hv0.x + w0.y * hv0.y + w0.z * hv0.z + w0.w * hv0.w
                       + w1.x * hv1.x + w1.y * hv1.y + w1.z * hv1.z + w1.w * hv1.w;
            }
        }
#pragma unroll
        for (int r = 0; r < MAXR; r++) {
            float v = acc[r];
            v += __shfl_xor_sync(0xffffffffu, v, 16);
            v += __shfl_xor_sync(0xffffffffu, v, 8);
            v += __shfl_xor_sync(0xffffffffu, v, 4);
            v += __shfl_xor_sync(0xffffffffu, v, 2);
            v += __shfl_xor_sync(0xffffffffu, v, 1);
            if (lane == 0) sPart[r][wid] = v;
        }
        __syncthreads();
        if (tid < nr) {
            float s = sPart[tid][0];
#pragma unroll
            for (int w = 1; w < 8; w++) s += sPart[tid][w];
            float z = s + sBfh[tid] + xf_v;
            float f = 1.f / (1.f + __expf(-z));
            sF[tid]    = f;
            sHold[tid] = h_own;
            d_gbuf[r0 + tid] = f * h_own;
        }
        gen += 1;
        gbar(gen);

        // ============ phase B : h_hat = tanh(Whf g + bhf + xh); update =====
        float xh_v = 0.f;
        if (tid < nr) xh_v = __ldg(&d_XH[(size_t)t * Hn + r0 + tid]);
        float4 gv0 = __ldcg((const float4 *)&d_gbuf[c0]);
        float4 gv1 = __ldcg((const float4 *)&d_gbuf[c0 + 4]);

#pragma unroll
        for (int r = 0; r < MAXR; r++) acc[r] = 0.f;
#pragma unroll
        for (int r = 0; r < MAXR; r++) {
            if (r < nr) {
                const float4* wp = (const float4 *)(sWh + r * Hn + c0);
                float4 w0 = wp[0], w1 = wp[1];
                acc[r] = w0.x * gv0.x + w0.y * gv0.y + w0.z * gv0.z + w0.w * gv0.w
                       + w1.x * gv1.x + w1.y * gv1.y + w1.z * gv1.z + w1.w * gv1.w;
            }
        }
#pragma unroll
        for (int r = 0; r < MAXR; r++) {
            float v = acc[r];
            v += __shfl_xor_sync(0xffffffffu, v, 16);
            v += __shfl_xor_sync(0xffffffffu, v, 8);
            v += __shfl_xor_sync(0xffffffffu, v, 4);
            v += __shfl_xor_sync(0xffffffffu, v, 2);
            v += __shfl_xor_sync(0xffffffffu, v, 1);
            if (lane == 0) sPart[r][wid] = v;
        }
        __syncthreads();
        if (tid < nr) {
            float s = sPart[tid][0];
#pragma unroll
            for (int w = 1; w < 8; w++) s += sPart[tid][w];
            float hh = tanhf(s + sBhf[tid] + xh_v);
            float f  = sF[tid];
            float ho = sHold[tid];
            float hn = ho + f * (hh - ho);     // (1-f)*h + f*h_hat
            int row  = r0 + tid;
            out[(size_t)t * Hn + row] = hn;
            d_hbuf[row] = hn;
            if (t == SEQ - 1) out[(size_t)SEQ * Hn + row] = hn;  // h_final
        }
        gen += 1;
        gbar(gen);
    }
}

// ------------------------------------------------------------------
extern "C" void kernel_launch(void* const* d_in, const int* in_sizes, int n_in,
                              void* d_out, int out_size)
{
    const float* x   = (const float *)d_in[0];
    const float* h0  = (const float *)d_in[1];
    const float* Wfx = (const float *)d_in[2];
    const float* bfx = (const float *)d_in[3];
    const float* Wfh = (const float *)d_in[4];
    const float* bfh = (const float *)d_in[5];
    const float* Whf = (const float *)d_in[6];
    const float* bhf = (const float *)d_in[7];
    const float* Whx = (const float *)d_in[8];
    const float* bhx = (const float *)d_in[9];
    float* out = (float *)d_out;

    (void)in_sizes; (void)n_in; (void)out_size;

    const size_t smem = (size_t)MAXR * Hn * 2 * sizeof(float);  // 229376 B
    cudaFuncSetAttribute(mgu_scan, cudaFuncAttributeMaxDynamicSharedMemorySize,
                         (int)smem);

    mgu_gemm<<<dim3(16, 16, 2), 256>>>(x, Wfx, bfx, Whx, bhx);
    mgu_scan<<<NBLK, TPB, smem>>>(h0, Wfh, bfh, Whf, bhf, out);
}

// round 3
// speedup vs baseline: 1.2024x; 1.2024x over previous
#include <cuda_runtime.h>
#include <math.h>

#define Hn   2048
#define SEQ  2048
#define NBLK 148
#define TPB  288     // 256 worker threads (8 warps) + 1 aggregator warp
#define WTH  256     // worker threads per block
#define CPT  8       // Hn / WTH columns per thread
#define MAXR 14      // max rows per block: ceil(2048/148)

// ------------------------------------------------------------------
// Static device scratch (no cudaMalloc allowed)
// ------------------------------------------------------------------
struct alignas(128) PadFlag { unsigned v; unsigned pad[31]; };

__device__ float d_XF[SEQ * Hn];     // x @ Wfx^T + bfx
__device__ float d_XH[SEQ * Hn];     // x @ Whx^T + bhx
__device__ float d_hbuf[Hn];         // hidden state (cross-block)
__device__ float d_gbuf[Hn];         // f * h (cross-block)
__device__ PadFlag  d_arrive[NBLK];  // per-block arrival generation (zero-init)
__device__ unsigned d_epoch;         // published by aggregator warp (zero-init)

// worker-only block barrier (named barrier 1, 8 warps = 256 threads)
__device__ __forceinline__ void wbar() {
    asm volatile("bar.sync 1, %0;" :: "n"(WTH) : "memory");
}

__device__ __forceinline__ void st_rel(unsigned* p, unsigned v) {
    asm volatile("st.release.gpu.global.u32 [%0], %1;" :: "l"(p), "r"(v) : "memory");
}
__device__ __forceinline__ unsigned ld_acq(const unsigned* p) {
    unsigned v;
    asm volatile("ld.acquire.gpu.global.u32 %0, [%1];" : "=r"(v) : "l"(p) : "memory");
    return v;
}

// Worker-side grid barrier: publish own arrival, wait for epoch.
// wait=false on the very last barrier (store-only).
__device__ __forceinline__ void gbar(unsigned gen, int b, bool wait) {
    wbar();                                 // order all worker threads' writes
    if (threadIdx.x == 0) {
        st_rel(&d_arrive[b].v, gen);
        if (wait) {
            while ((int)(ld_acq(&d_epoch) - gen) < 0) { }
        }
    }
    wbar();
}

// ------------------------------------------------------------------
// Precompute GEMM:  C[s][n] = sum_k x[s][k] * W[n][k] + bias[n]
// ------------------------------------------------------------------
__global__ __launch_bounds__(256, 2) void mgu_gemm(
    const float* __restrict__ x,
    const float* __restrict__ Wfx, const float* __restrict__ bfx,
    const float* __restrict__ Whx, const float* __restrict__ bhx)
{
    const float* __restrict__ W    = (blockIdx.z == 0) ? Wfx : Whx;
    const float* __restrict__ bias = (blockIdx.z == 0) ? bfx : bhx;
    float* __restrict__ C          = (blockIdx.z == 0) ? d_XF : d_XH;

    __shared__ float As[16][132];
    __shared__ float Bs[16][132];

    const int bm  = blockIdx.y * 128;
    const int bn  = blockIdx.x * 128;
    const int tid = threadIdx.x;
    const int tr  = (tid >> 4) << 3;
    const int tc  = (tid & 15) << 3;

    float acc[8][8];
#pragma unroll
    for (int i = 0; i < 8; i++)
#pragma unroll
        for (int j = 0; j < 8; j++) acc[i][j] = 0.f;

    for (int k0 = 0; k0 < 2048; k0 += 16) {
#pragma unroll
        for (int i = 0; i < 2; i++) {
            int q   = tid + (i << 8);
            int row = q >> 2;
            int kq  = (q & 3) << 2;
            float4 va = *(const float4 *)(x + (size_t)(bm + row) * 2048 + k0 + kq);
            As[kq + 0][row] = va.x; As[kq + 1][row] = va.y;
            As[kq + 2][row] = va.z; As[kq + 3][row] = va.w;
            float4 vb = *(const float4 *)(W + (size_t)(bn + row) * 2048 + k0 + kq);
            Bs[kq + 0][row] = vb.x; Bs[kq + 1][row] = vb.y;
            Bs[kq + 2][row] = vb.z; Bs[kq + 3][row] = vb.w;
        }
        __syncthreads();
#pragma unroll
        for (int k = 0; k < 16; k++) {
            float a[8], b[8];
            *(float4 *)(a)     = *(const float4 *)&As[k][tr];
            *(float4 *)(a + 4) = *(const float4 *)&As[k][tr + 4];
            *(float4 *)(b)     = *(const float4 *)&Bs[k][tc];
            *(float4 *)(b + 4) = *(const float4 *)&Bs[k][tc + 4];
#pragma unroll
            for (int i = 0; i < 8; i++)
#pragma unroll
                for (int j = 0; j < 8; j++) acc[i][j] += a[i] * b[j];
        }
        __syncthreads();
    }

    float bj[8];
#pragma unroll
    for (int j = 0; j < 8; j++) bj[j] = __ldg(&bias[bn + tc + j]);
#pragma unroll
    for (int i = 0; i < 8; i++) {
        float4 v0 = make_float4(acc[i][0] + bj[0], acc[i][1] + bj[1],
                                acc[i][2] + bj[2], acc[i][3] + bj[3]);
        float4 v1 = make_float4(acc[i][4] + bj[4], acc[i][5] + bj[5],
                                acc[i][6] + bj[6], acc[i][7] + bj[7]);
        size_t off = (size_t)(bm + tr + i) * 2048 + bn + tc;
        *(float4 *)(C + off)     = v0;
        *(float4 *)(C + off + 4) = v1;
    }
}

// ------------------------------------------------------------------
// Persistent scan. 148 blocks, 1/SM. Warps 0-7 = workers; warp 8 of
// block 0 = barrier aggregator (other blocks' warp 8 exits).
// ------------------------------------------------------------------
__global__ __launch_bounds__(TPB, 1) void mgu_scan(
    const float* __restrict__ h0,
    const float* __restrict__ Wfh, const float* __restrict__ bfh,
    const float* __restrict__ Whf, const float* __restrict__ bhf,
    float* __restrict__ out)
{
    extern __shared__ float sW[];
    __shared__ float sPart[MAXR][8];
    __shared__ float sF[MAXR];
    __shared__ float sHold[MAXR];
    __shared__ float sBfh[MAXR];
    __shared__ float sBhf[MAXR];

    const int b   = blockIdx.x;
    const int tid = threadIdx.x;
    const int total_gens = 1 + 2 * SEQ;

    // ---------------- aggregator warp (block 0, warp 8) ----------------
    if (tid >= WTH) {
        if (b != 0) return;
        const int lane = tid & 31;
        unsigned base = *(volatile unsigned *)&d_epoch;
        for (int i = 1; i <= total_gens; i++) {
            unsigned g = base + (unsigned)i;
            bool all_ok;
            do {
                bool mine = true;
#pragma unroll
                for (int k = 0; k < 5; k++) {
                    int idx = lane + (k << 5);
                    if (idx < NBLK)
                        mine &= ((int)(ld_acq(&d_arrive[idx].v) - g) >= 0);
                }
                all_ok = __all_sync(0xffffffffu, mine);
            } while (!all_ok);
            if (lane == 0) st_rel(&d_epoch, g);
        }
        return;
    }

    // ---------------- worker warps (8 warps, 256 threads) ----------------
    const int r0 = (b * Hn) / NBLK;
    const int r1 = ((b + 1) * Hn) / NBLK;
    const int nr = r1 - r0;                 // 13 or 14

    float* sWf = sW;                        // Wfh rows
    float* sWh = sW + nr * Hn;              // Whf rows

    {   // load weight rows into SMEM (coalesced float4)
        const float4* gf = (const float4 *)(Wfh + (size_t)r0 * Hn);
        const float4* gh = (const float4 *)(Whf + (size_t)r0 * Hn);
        float4* sf4 = (float4 *)sWf;
        float4* sh4 = (float4 *)sWh;
        const int n4 = nr * (Hn / 4);
        for (int i = tid; i < n4; i += WTH) { sf4[i] = gf[i]; sh4[i] = gh[i]; }
    }
    if (tid < nr) {
        sBfh[tid]  = bfh[r0 + tid];
        sBhf[tid]  = bhf[r0 + tid];
        sHold[tid] = h0[r0 + tid];          // own hidden chunk lives in SMEM
    }

    // init global hidden state
    for (int i = b * WTH + tid; i < Hn; i += NBLK * WTH) d_hbuf[i] = h0[i];

    unsigned gen = *(volatile unsigned *)&d_arrive[b].v;  // own flag: monotonic base
    gen += 1;
    gbar(gen, b, true);

    const int c0   = tid * CPT;
    const int wid  = tid >> 5;
    const int lane = tid & 31;

    // prefetch xf/xh for t=0
    float xf_c = 0.f, xh_c = 0.f;
    if (tid < nr) {
        xf_c = __ldg(&d_XF[r0 + tid]);
        xh_c = __ldg(&d_XH[r0 + tid]);
    }

    for (int t = 0; t < SEQ; t++) {
        // ===== phase A : f = sigmoid(xf + Wfh h + bfh);  g = f*h =====
        float4 hv0 = __ldcg((const float4 *)&d_hbuf[c0]);
        float4 hv1 = __ldcg((const float4 *)&d_hbuf[c0 + 4]);

        float acc[MAXR];
#pragma unroll
        for (int r = 0; r < MAXR; r++) acc[r] = 0.f;
#pragma unroll
        for (int r = 0; r < MAXR; r++) {
            if (r < nr) {
                const float4* wp = (const float4 *)(sWf + r * Hn + c0);
                float4 w0 = wp[0], w1 = wp[1];
                acc[r] = w0.x * hv0.x + w0.y * hv0.y + w0.z * hv0.z + w0.w * hv0.w
                       + w1.x * hv1.x + w1.y * hv1.y + w1.z * hv1.z + w1.w * hv1.w;
            }
        }
#pragma unroll
        for (int r = 0; r < MAXR; r++) {
            float v = acc[r];
            v += __shfl_xor_sync(0xffffffffu, v, 16);
            v += __shfl_xor_sync(0xffffffffu, v, 8);
            v += __shfl_xor_sync(0xffffffffu, v, 4);
            v += __shfl_xor_sync(0xffffffffu, v, 2);
            v += __shfl_xor_sync(0xffffffffu, v, 1);
            if (lane == 0) sPart[r][wid] = v;
        }
        wbar();
        if (tid < nr) {
            float s = sPart[tid][0];
#pragma unroll
            for (int w = 1; w < 8; w++) s += sPart[tid][w];
            float z = s + sBfh[tid] + xf_c;
            float f = 1.f / (1.f + __expf(-z));
            sF[tid] = f;
            __stcg(&d_gbuf[r0 + tid], f * sHold[tid]);
        }
        gen += 1;
        gbar(gen, b, true);

        // ===== phase B : h_hat = tanh(Whf g + bhf + xh); update =====
        float4 gv0 = __ldcg((const float4 *)&d_gbuf[c0]);
        float4 gv1 = __ldcg((const float4 *)&d_gbuf[c0 + 4]);

        // prefetch next step's xf/xh while GEMV runs
        float xf_n = 0.f, xh_n = 0.f;
        if (tid < nr && t + 1 < SEQ) {
            xf_n = __ldg(&d_XF[(size_t)(t + 1) * Hn + r0 + tid]);
            xh_n = __ldg(&d_XH[(size_t)(t + 1) * Hn + r0 + tid]);
        }

#pragma unroll
        for (int r = 0; r < MAXR; r++) acc[r] = 0.f;
#pragma unroll
        for (int r = 0; r < MAXR; r++) {
            if (r < nr) {
                const float4* wp = (const float4 *)(sWh + r * Hn + c0);
                float4 w0 = wp[0], w1 = wp[1];
                acc[r] = w0.x * gv0.x + w0.y * gv0.y + w0.z * gv0.z + w0.w * gv0.w
                       + w1.x * gv1.x + w1.y * gv1.y + w1.z * gv1.z + w1.w * gv1.w;
            }
        }
#pragma unroll
        for (int r = 0; r < MAXR; r++) {
            float v = acc[r];
            v += __shfl_xor_sync(0xffffffffu, v, 16);
            v += __shfl_xor_sync(0xffffffffu, v, 8);
            v += __shfl_xor_sync(0xffffffffu, v, 4);
            v += __shfl_xor_sync(0xffffffffu, v, 2);
            v += __shfl_xor_sync(0xffffffffu, v, 1);
            if (lane == 0) sPart[r][wid] = v;
        }
        wbar();
        if (tid < nr) {
            float s = sPart[tid][0];
#pragma unroll
            for (int w = 1; w < 8; w++) s += sPart[tid][w];
            float z  = s + sBhf[tid] + xh_c;
            float e2 = __expf(2.f * z);
            float hh = 1.f - 2.f / (e2 + 1.f);      // tanh(z)
            float f  = sF[tid];
            float ho = sHold[tid];
            float hn = ho + f * (hh - ho);          // (1-f)*h + f*h_hat
            sHold[tid] = hn;
            int row = r0 + tid;
            out[(size_t)t * Hn + row] = hn;
            __stcg(&d_hbuf[row], hn);
            if (t == SEQ - 1) out[(size_t)SEQ * Hn + row] = hn;  // h_final
        }
        xf_c = xf_n;
        xh_c = xh_n;
        gen += 1;
        gbar(gen, b, t < SEQ - 1);   // last barrier is store-only
    }
}

// ------------------------------------------------------------------
extern "C" void kernel_launch(void* const* d_in, const int* in_sizes, int n_in,
                              void* d_out, int out_size)
{
    const float* x   = (const float *)d_in[0];
    const float* h0  = (const float *)d_in[1];
    const float* Wfx = (const float *)d_in[2];
    const float* bfx = (const float *)d_in[3];
    const float* Wfh = (const float *)d_in[4];
    const float* bfh = (const float *)d_in[5];
    const float* Whf = (const float *)d_in[6];
    const float* bhf = (const float *)d_in[7];
    const float* Whx = (const float *)d_in[8];
    const float* bhx = (const float *)d_in[9];
    float* out = (float *)d_out;

    (void)in_sizes; (void)n_in; (void)out_size;

    const size_t smem = (size_t)MAXR * Hn * 2 * sizeof(float);  // 229376 B
    cudaFuncSetAttribute(mgu_scan, cudaFuncAttributeMaxDynamicSharedMemorySize,
                         (int)smem);

    mgu_gemm<<<dim3(16, 16, 2), 256>>>(x, Wfx, bfx, Whx, bhx);
    mgu_scan<<<NBLK, TPB, smem>>>(h0, Wfh, bfh, Whf, bhf, out);
}

// round 4
// speedup vs baseline: 2.0924x; 1.7402x over previous
#include <cuda_runtime.h>
#include <math.h>

#define Hn   2048
#define SEQ  2048
#define NBLK 148
#define TPB  512     // 16 warps; threads 0-255 = row-half 0, 256-511 = row-half 1
#define CPT  8       // columns per thread (2048 / 256)
#define MAXR 14      // max rows per block
#define RPH  7       // rows per half

// ------------------------------------------------------------------
// Static device scratch (no cudaMalloc allowed)
// ------------------------------------------------------------------
__device__ float d_XF[SEQ * Hn];   // x @ Wfx^T + bfx
__device__ float d_XH[SEQ * Hn];   // x @ Whx^T + bhx
__device__ float d_hbuf[Hn];       // hidden state (cross-block)
__device__ float d_gbuf[Hn];       // f * h (cross-block)
__device__ unsigned d_count = 0;   // monotonic barrier arrival counter
__device__ unsigned d_base  = 0;   // counter value at start of this run

__device__ __forceinline__ void red_arrive(unsigned* p) {
    asm volatile("red.release.gpu.global.add.u32 [%0], %1;"
                 :: "l"(p), "r"(1u) : "memory");
}
__device__ __forceinline__ unsigned ld_acq(const unsigned* p) {
    unsigned v;
    asm volatile("ld.acquire.gpu.global.u32 %0, [%1];" : "=r"(v) : "l"(p) : "memory");
    return v;
}

// grid barrier: RED arrival by tid0, poll same counter until target reached
__device__ __forceinline__ void gbar(unsigned target, bool wait) {
    __syncthreads();                    // order all threads' writes before release
    if (threadIdx.x == 0) {
        red_arrive(&d_count);
        if (wait) {
            while ((int)(ld_acq(&d_count) - target) < 0) { }
        }
    }
    __syncthreads();
}

// ------------------------------------------------------------------
// Precompute GEMM:  C[s][n] = sum_k x[s][k] * W[n][k] + bias[n]
// ------------------------------------------------------------------
__global__ __launch_bounds__(256, 2) void mgu_gemm(
    const float* __restrict__ x,
    const float* __restrict__ Wfx, const float* __restrict__ bfx,
    const float* __restrict__ Whx, const float* __restrict__ bhx)
{
    const float* __restrict__ W    = (blockIdx.z == 0) ? Wfx : Whx;
    const float* __restrict__ bias = (blockIdx.z == 0) ? bfx : bhx;
    float* __restrict__ C          = (blockIdx.z == 0) ? d_XF : d_XH;

    __shared__ float As[16][132];
    __shared__ float Bs[16][132];

    const int bm  = blockIdx.y * 128;
    const int bn  = blockIdx.x * 128;
    const int tid = threadIdx.x;
    const int tr  = (tid >> 4) << 3;
    const int tc  = (tid & 15) << 3;

    float acc[8][8];
#pragma unroll
    for (int i = 0; i < 8; i++)
#pragma unroll
        for (int j = 0; j < 8; j++) acc[i][j] = 0.f;

    for (int k0 = 0; k0 < 2048; k0 += 16) {
#pragma unroll
        for (int i = 0; i < 2; i++) {
            int q   = tid + (i << 8);
            int row = q >> 2;
            int kq  = (q & 3) << 2;
            float4 va = *(const float4 *)(x + (size_t)(bm + row) * 2048 + k0 + kq);
            As[kq + 0][row] = va.x; As[kq + 1][row] = va.y;
            As[kq + 2][row] = va.z; As[kq + 3][row] = va.w;
            float4 vb = *(const float4 *)(W + (size_t)(bn + row) * 2048 + k0 + kq);
            Bs[kq + 0][row] = vb.x; Bs[kq + 1][row] = vb.y;
            Bs[kq + 2][row] = vb.z; Bs[kq + 3][row] = vb.w;
        }
        __syncthreads();
#pragma unroll
        for (int k = 0; k < 16; k++) {
            float a[8], b[8];
            *(float4 *)(a)     = *(const float4 *)&As[k][tr];
            *(float4 *)(a + 4) = *(const float4 *)&As[k][tr + 4];
            *(float4 *)(b)     = *(const float4 *)&Bs[k][tc];
            *(float4 *)(b + 4) = *(const float4 *)&Bs[k][tc + 4];
#pragma unroll
            for (int i = 0; i < 8; i++)
#pragma unroll
                for (int j = 0; j < 8; j++) acc[i][j] += a[i] * b[j];
        }
        __syncthreads();
    }

    float bj[8];
#pragma unroll
    for (int j = 0; j < 8; j++) bj[j] = __ldg(&bias[bn + tc + j]);
#pragma unroll
    for (int i = 0; i < 8; i++) {
        float4 v0 = make_float4(acc[i][0] + bj[0], acc[i][1] + bj[1],
                                acc[i][2] + bj[2], acc[i][3] + bj[3]);
        float4 v1 = make_float4(acc[i][4] + bj[4], acc[i][5] + bj[5],
                                acc[i][6] + bj[6], acc[i][7] + bj[7]);
        size_t off = (size_t)(bm + tr + i) * 2048 + bn + tc;
        *(float4 *)(C + off)     = v0;
        *(float4 *)(C + off + 4) = v1;
    }
}

// ------------------------------------------------------------------
// Persistent scan. 148 blocks (1/SM), 512 threads.
// Half 0 (warps 0-7) computes rows 0-6 of the block's slice,
// half 1 (warps 8-15) rows 7-13. Each thread covers 8 columns.
// ------------------------------------------------------------------
__global__ __launch_bounds__(TPB, 1) void mgu_scan(
    const float* __restrict__ h0,
    const float* __restrict__ Wfh, const float* __restrict__ bfh,
    const float* __restrict__ Whf, const float* __restrict__ bhf,
    float* __restrict__ out)
{
    extern __shared__ float sW[];
    __shared__ float sPart[MAXR][8];
    __shared__ float sF[MAXR];
    __shared__ float sHold[MAXR];
    __shared__ float sBfh[MAXR];
    __shared__ float sBhf[MAXR];
    __shared__ unsigned sBase;

    const int b   = blockIdx.x;
    const int tid = threadIdx.x;
    const int r0  = (b * Hn) / NBLK;
    const int r1  = ((b + 1) * Hn) / NBLK;
    const int nr  = r1 - r0;               // 13 or 14

    float* sWf = sW;                        // Wfh rows
    float* sWh = sW + nr * Hn;              // Whf rows

    if (tid == 0) sBase = *(volatile unsigned *)&d_base;

    {   // load weight rows into SMEM (coalesced float4)
        const float4* gf = (const float4 *)(Wfh + (size_t)r0 * Hn);
        const float4* gh = (const float4 *)(Whf + (size_t)r0 * Hn);
        float4* sf4 = (float4 *)sWf;
        float4* sh4 = (float4 *)sWh;
        const int n4 = nr * (Hn / 4);
        for (int i = tid; i < n4; i += TPB) { sf4[i] = gf[i]; sh4[i] = gh[i]; }
    }
    if (tid < nr) {
        sBfh[tid]  = bfh[r0 + tid];
        sBhf[tid]  = bhf[r0 + tid];
        sHold[tid] = h0[r0 + tid];
    }
    for (int i = b * TPB + tid; i < Hn; i += NBLK * TPB) d_hbuf[i] = h0[i];

    __syncthreads();
    unsigned tgt = sBase;                    // barrier target accumulator
    tgt += NBLK;
    gbar(tgt, true);                         // weights + h0 ready everywhere

    const int half  = tid >> 8;              // 0 or 1
    const int tid2  = tid & 255;
    const int c0    = tid2 * CPT;
    const int wid8  = (tid >> 5) & 7;        // warp index within half
    const int lane  = tid & 31;
    const int rbase = half * RPH;

    // prefetch xf/xh for t=0
    float xf_c = 0.f, xh_c = 0.f;
    if (tid < nr) {
        xf_c = __ldg(&d_XF[r0 + tid]);
        xh_c = __ldg(&d_XH[r0 + tid]);
    }

    for (int t = 0; t < SEQ; t++) {
        // ===== phase A : f = sigmoid(xf + Wfh h + bfh);  g = f*h =====
        float4 hv0 = __ldcg((const float4 *)&d_hbuf[c0]);
        float4 hv1 = __ldcg((const float4 *)&d_hbuf[c0 + 4]);

        float acc[RPH];
#pragma unroll
        for (int r = 0; r < RPH; r++) {
            int row = rbase + r;
            float a = 0.f;
            if (row < nr) {
                const float4* wp = (const float4 *)(sWf + row * Hn + c0);
                float4 w0 = wp[0], w1 = wp[1];
                a = w0.x * hv0.x + w0.y * hv0.y + w0.z * hv0.z + w0.w * hv0.w
                  + w1.x * hv1.x + w1.y * hv1.y + w1.z * hv1.z + w1.w * hv1.w;
            }
            acc[r] = a;
        }
#pragma unroll
        for (int r = 0; r < RPH; r++) {
            float v = acc[r];
            v += __shfl_xor_sync(0xffffffffu, v, 16);
            v += __shfl_xor_sync(0xffffffffu, v, 8);
            v += __shfl_xor_sync(0xffffffffu, v, 4);
            v += __shfl_xor_sync(0xffffffffu, v, 2);
            v += __shfl_xor_sync(0xffffffffu, v, 1);
            int row = rbase + r;
            if (lane == 0 && row < nr) sPart[row][wid8] = v;
        }
        __syncthreads();
        if (tid < nr) {
            float4 p0 = *(const float4 *)&sPart[tid][0];
            float4 p1 = *(const float4 *)&sPart[tid][4];
            float s = (p0.x + p0.y) + (p0.z + p0.w)
                    + (p1.x + p1.y) + (p1.z + p1.w);
            float z = s + sBfh[tid] + xf_c;
            float f = 1.f / (1.f + __expf(-z));
            sF[tid] = f;
            __stcg(&d_gbuf[r0 + tid], f * sHold[tid]);
        }
        tgt += NBLK;
        gbar(tgt, true);

        // ===== phase B : h_hat = tanh(Whf g + bhf + xh); update =====
        float4 gv0 = __ldcg((const float4 *)&d_gbuf[c0]);
        float4 gv1 = __ldcg((const float4 *)&d_gbuf[c0 + 4]);

        float xf_n = 0.f, xh_n = 0.f;      // prefetch next step's x-projections
        if (tid < nr && t + 1 < SEQ) {
            xf_n = __ldg(&d_XF[(size_t)(t + 1) * Hn + r0 + tid]);
            xh_n = __ldg(&d_XH[(size_t)(t + 1) * Hn + r0 + tid]);
        }

#pragma unroll
        for (int r = 0; r < RPH; r++) {
            int row = rbase + r;
            float a = 0.f;
            if (row < nr) {
                const float4* wp = (const float4 *)(sWh + row * Hn + c0);
                float4 w0 = wp[0], w1 = wp[1];
                a = w0.x * gv0.x + w0.y * gv0.y + w0.z * gv0.z + w0.w * gv0.w
                  + w1.x * gv1.x + w1.y * gv1.y + w1.z * gv1.z + w1.w * gv1.w;
            }
            acc[r] = a;
        }
#pragma unroll
        for (int r = 0; r < RPH; r++) {
            float v = acc[r];
            v += __shfl_xor_sync(0xffffffffu, v, 16);
            v += __shfl_xor_sync(0xffffffffu, v, 8);
            v += __shfl_xor_sync(0xffffffffu, v, 4);
            v += __shfl_xor_sync(0xffffffffu, v, 2);
            v += __shfl_xor_sync(0xffffffffu, v, 1);
            int row = rbase + r;
            if (lane == 0 && row < nr) sPart[row][wid8] = v;
        }
        __syncthreads();
        if (tid < nr) {
            float4 p0 = *(const float4 *)&sPart[tid][0];
            float4 p1 = *(const float4 *)&sPart[tid][4];
            float s = (p0.x + p0.y) + (p0.z + p0.w)
                    + (p1.x + p1.y) + (p1.z + p1.w);
            float z  = s + sBhf[tid] + xh_c;
            float e2 = __expf(2.f * z);
            float hh = 1.f - 2.f / (e2 + 1.f);      // tanh(z)
            float f  = sF[tid];
            float ho = sHold[tid];
            float hn = ho + f * (hh - ho);          // (1-f)*h + f*h_hat
            sHold[tid] = hn;
            int row = r0 + tid;
            out[(size_t)t * Hn + row] = hn;
            __stcg(&d_hbuf[row], hn);
            if (t == SEQ - 1) out[(size_t)SEQ * Hn + row] = hn;  // h_final
        }
        xf_c = xf_n;
        xh_c = xh_n;
        tgt += NBLK;
        gbar(tgt, t < SEQ - 1);                // last barrier: arrive only
    }

    // advance the persistent barrier base for the next graph replay
    if (b == 0 && tid == 0) {
        *(volatile unsigned *)&d_base = sBase + (unsigned)(1 + 2 * SEQ) * NBLK;
    }
}

// ------------------------------------------------------------------
extern "C" void kernel_launch(void* const* d_in, const int* in_sizes, int n_in,
                              void* d_out, int out_size)
{
    const float* x   = (const float *)d_in[0];
    const float* h0  = (const float *)d_in[1];
    const float* Wfx = (const float *)d_in[2];
    const float* bfx = (const float *)d_in[3];
    const float* Wfh = (const float *)d_in[4];
    const float* bfh = (const float *)d_in[5];
    const float* Whf = (const float *)d_in[6];
    const float* bhf = (const float *)d_in[7];
    const float* Whx = (const float *)d_in[8];
    const float* bhx = (const float *)d_in[9];
    float* out = (float *)d_out;

    (void)in_sizes; (void)n_in; (void)out_size;

    const size_t smem = (size_t)MAXR * Hn * 2 * sizeof(float);  // 229376 B
    cudaFuncSetAttribute(mgu_scan, cudaFuncAttributeMaxDynamicSharedMemorySize,
                         (int)smem);

    mgu_gemm<<<dim3(16, 16, 2), 256>>>(x, Wfx, bfx, Whx, bhx);
    mgu_scan<<<NBLK, TPB, smem>>>(h0, Wfh, bfh, Whf, bhf, out);
}

// round 6
// speedup vs baseline: 2.2153x; 1.0587x over previous
#include <cuda_runtime.h>
#include <math.h>

#define Hn   2048
#define SEQ  2048
#define NBLK 148
#define TPB  288     // 8 worker warps (256) + 1 poller warp
#define WTH  256
#define MAXR 14      // max rows per block: ceil(2048/148)

// ------------------------------------------------------------------
// Static device scratch (no cudaMalloc allowed)
// ------------------------------------------------------------------
__device__ float d_XF[SEQ * Hn];   // x @ Wfx^T + bfx
__device__ float d_XH[SEQ * Hn];   // x @ Whx^T + bhx
__device__ float d_hbuf[Hn];       // hidden state (cross-block)
__device__ float d_gbuf[Hn];       // f * h (cross-block)
__device__ unsigned d_count = 0;   // monotonic barrier arrival counter
__device__ unsigned d_base  = 0;   // counter value at start of this run

__device__ __forceinline__ void red_arrive(unsigned* p) {
    asm volatile("red.release.gpu.global.add.u32 [%0], %1;"
                 :: "l"(p), "r"(1u) : "memory");
}
__device__ __forceinline__ unsigned ld_acq(const unsigned* p) {
    unsigned v;
    asm volatile("ld.acquire.gpu.global.u32 %0, [%1];" : "=r"(v) : "l"(p) : "memory");
    return v;
}
// workers-only barrier
__device__ __forceinline__ void bar1() {
    asm volatile("bar.sync 1, %0;" :: "n"(WTH) : "memory");
}
// workers + poller barrier
__device__ __forceinline__ void bar2() {
    asm volatile("bar.sync 2, %0;" :: "n"(TPB) : "memory");
}

// ------------------------------------------------------------------
// Precompute GEMM:  C[s][n] = sum_k x[s][k] * W[n][k] + bias[n]
// ------------------------------------------------------------------
__global__ __launch_bounds__(256, 2) void mgu_gemm(
    const float* __restrict__ x,
    const float* __restrict__ Wfx, const float* __restrict__ bfx,
    const float* __restrict__ Whx, const float* __restrict__ bhx)
{
    const float* __restrict__ W    = (blockIdx.z == 0) ? Wfx : Whx;
    const float* __restrict__ bias = (blockIdx.z == 0) ? bfx : bhx;
    float* __restrict__ C          = (blockIdx.z == 0) ? d_XF : d_XH;

    __shared__ float As[16][132];
    __shared__ float Bs[16][132];

    const int bm  = blockIdx.y * 128;
    const int bn  = blockIdx.x * 128;
    const int tid = threadIdx.x;
    const int tr  = (tid >> 4) << 3;
    const int tc  = (tid & 15) << 3;

    float acc[8][8];
#pragma unroll
    for (int i = 0; i < 8; i++)
#pragma unroll
        for (int j = 0; j < 8; j++) acc[i][j] = 0.f;

    for (int k0 = 0; k0 < 2048; k0 += 16) {
#pragma unroll
        for (int i = 0; i < 2; i++) {
            int q   = tid + (i << 8);
            int row = q >> 2;
            int kq  = (q & 3) << 2;
            float4 va = *(const float4 *)(x + (size_t)(bm + row) * 2048 + k0 + kq);
            As[kq + 0][row] = va.x; As[kq + 1][row] = va.y;
            As[kq + 2][row] = va.z; As[kq + 3][row] = va.w;
            float4 vb = *(const float4 *)(W + (size_t)(bn + row) * 2048 + k0 + kq);
            Bs[kq + 0][row] = vb.x; Bs[kq + 1][row] = vb.y;
            Bs[kq + 2][row] = vb.z; Bs[kq + 3][row] = vb.w;
        }
        __syncthreads();
#pragma unroll
        for (int k = 0; k < 16; k++) {
            float a[8], bvv[8];
            *(float4 *)(a)     = *(const float4 *)&As[k][tr];
            *(float4 *)(a + 4) = *(const float4 *)&As[k][tr + 4];
            *(float4 *)(bvv)     = *(const float4 *)&Bs[k][tc];
            *(float4 *)(bvv + 4) = *(const float4 *)&Bs[k][tc + 4];
#pragma unroll
            for (int i = 0; i < 8; i++)
#pragma unroll
                for (int j = 0; j < 8; j++) acc[i][j] += a[i] * bvv[j];
        }
        __syncthreads();
    }

    float bj[8];
#pragma unroll
    for (int j = 0; j < 8; j++) bj[j] = __ldg(&bias[bn + tc + j]);
#pragma unroll
    for (int i = 0; i < 8; i++) {
        float4 v0 = make_float4(acc[i][0] + bj[0], acc[i][1] + bj[1],
                                acc[i][2] + bj[2], acc[i][3] + bj[3]);
        float4 v1 = make_float4(acc[i][4] + bj[4], acc[i][5] + bj[5],
                                acc[i][6] + bj[6], acc[i][7] + bj[7]);
        size_t off = (size_t)(bm + tr + i) * 2048 + bn + tc;
        *(float4 *)(C + off)     = v0;
        *(float4 *)(C + off + 4) = v1;
    }
}

// ------------------------------------------------------------------
// Persistent scan. 148 blocks (1/SM). Warps 0-7 = workers (each
// thread: 14 rows x 8 cols as two conflict-free 4-col chunks).
// Warp 8 = poller: polls the global counter, releases workers via
// named barrier 2. Weights preloaded into registers during the
// barrier window so crossbar streaming hides under sync latency.
// ------------------------------------------------------------------
__global__ __launch_bounds__(TPB, 1) void mgu_scan(
    const float* __restrict__ h0,
    const float* __restrict__ Wfh, const float* __restrict__ bfh,
    const float* __restrict__ Whf, const float* __restrict__ bhf,
    float* __restrict__ out)
{
    extern __shared__ float sW[];
    __shared__ float sPart[MAXR][8];
    __shared__ float sF[MAXR];
    __shared__ float sHold[MAXR];
    __shared__ float sBfh[MAXR];
    __shared__ float sBhf[MAXR];
    __shared__ unsigned sBase;

    const int b   = blockIdx.x;
    const int tid = threadIdx.x;
    const int r0  = (b * Hn) / NBLK;
    const int r1  = ((b + 1) * Hn) / NBLK;
    const int nr  = r1 - r0;               // 13 or 14

    float* sWf = sW;                        // Wfh rows
    float* sWh = sW + nr * Hn;              // Whf rows

    if (tid == 0) sBase = *(volatile unsigned *)&d_base;

    {   // stage weight rows into SMEM (coalesced float4)
        const float4* gf = (const float4 *)(Wfh + (size_t)r0 * Hn);
        const float4* gh = (const float4 *)(Whf + (size_t)r0 * Hn);
        float4* sf4 = (float4 *)sWf;
        float4* sh4 = (float4 *)sWh;
        const int n4 = nr * (Hn / 4);
        for (int i = tid; i < n4; i += TPB) { sf4[i] = gf[i]; sh4[i] = gh[i]; }
    }
    if (tid < nr) {
        sBfh[tid]  = bfh[r0 + tid];
        sBhf[tid]  = bhf[r0 + tid];
        sHold[tid] = h0[r0 + tid];
    }
    for (int i = b * TPB + tid; i < Hn; i += NBLK * TPB) d_hbuf[i] = h0[i];

    __syncthreads();
    const unsigned base = sBase;
    if (tid == 0) red_arrive(&d_count);      // gen 1: weights + h0 published

    // ---------------- poller warp ----------------
    if (tid >= WTH) {
        for (unsigned g = 1; g <= 2u * SEQ; g++) {
            if (tid == WTH) {
                unsigned target = base + g * (unsigned)NBLK;
                while ((int)(ld_acq(&d_count) - target) < 0) { }
            }
            bar2();
        }
        if (b == 0 && tid == WTH)
            *(volatile unsigned *)&d_base = base + 2u * SEQ * (unsigned)NBLK;
        return;
    }

    // ---------------- workers ----------------
    const int lane = tid & 31;
    const int wid  = tid >> 5;
    const int cA   = wid * 128 + lane * 4;          // conflict-free chunk 0
    const int cB   = 1024 + wid * 128 + lane * 4;   // conflict-free chunk 1

    float xf_c = 0.f, xh_c = 0.f;
    if (tid < nr) {
        xf_c = __ldg(&d_XF[r0 + tid]);
        xh_c = __ldg(&d_XH[r0 + tid]);
    }

    float4 wr[MAXR][2];
#pragma unroll
    for (int r = 0; r < MAXR; r++) {                // preload Wfh for t=0
        wr[r][0] = *(const float4 *)(sWf + r * Hn + cA);
        wr[r][1] = *(const float4 *)(sWf + r * Hn + cB);
    }
    bar2();                                          // gen 1 synced: h ready

    for (int t = 0; t < SEQ; t++) {
        // ===== phase A : f = sigmoid(xf + Wfh h + bfh);  g = f*h =====
        float4 hv0 = __ldcg((const float4 *)&d_hbuf[cA]);
        float4 hv1 = __ldcg((const float4 *)&d_hbuf[cB]);

        float acc[MAXR];
#pragma unroll
        for (int r = 0; r < MAXR; r++) {
            acc[r] = wr[r][0].x * hv0.x + wr[r][0].y * hv0.y
                   + wr[r][0].z * hv0.z + wr[r][0].w * hv0.w
                   + wr[r][1].x * hv1.x + wr[r][1].y * hv1.y
                   + wr[r][1].z * hv1.z + wr[r][1].w * hv1.w;
        }
        // paired butterfly reduction: 6 SHFL per 2 rows
#pragma unroll
        for (int p = 0; p < 7; p++) {
            float a = acc[2 * p], c = acc[2 * p + 1];
            a += __shfl_xor_sync(0xffffffffu, a, 16);
            c += __shfl_xor_sync(0xffffffffu, c, 16);
            float m = (lane < 16) ? a : c;
            m += __shfl_xor_sync(0xffffffffu, m, 8);
            m += __shfl_xor_sync(0xffffffffu, m, 4);
            m += __shfl_xor_sync(0xffffffffu, m, 2);
            m += __shfl_xor_sync(0xffffffffu, m, 1);
            if (lane == 0)       sPart[2 * p][wid]     = m;
            else if (lane == 16) sPart[2 * p + 1][wid] = m;
        }
        bar1();
        if (tid < nr) {
            float4 p0 = *(const float4 *)&sPart[tid][0];
            float4 p1 = *(const float4 *)&sPart[tid][4];
            float s = (p0.x + p0.y) + (p0.z + p0.w)
                    + (p1.x + p1.y) + (p1.z + p1.w);
            float z = s + sBfh[tid] + xf_c;
            float f = 1.f / (1.f + __expf(-z));
            sF[tid] = f;
            __stcg(&d_gbuf[r0 + tid], f * sHold[tid]);
        }
        bar1();
        if (tid == 0) red_arrive(&d_count);          // gen 2t+2
#pragma unroll
        for (int r = 0; r < MAXR; r++) {             // preload Whf (hidden under sync)
            wr[r][0] = *(const float4 *)(sWh + r * Hn + cA);
            wr[r][1] = *(const float4 *)(sWh + r * Hn + cB);
        }
        bar2();                                      // gen 2t+2 synced: g ready

        // ===== phase B : h_hat = tanh(Whf g + bhf + xh); update =====
        float4 gv0 = __ldcg((const float4 *)&d_gbuf[cA]);
        float4 gv1 = __ldcg((const float4 *)&d_gbuf[cB]);

        float xf_n = 0.f, xh_n = 0.f;                // prefetch next x-projections
        if (tid < nr && t + 1 < SEQ) {
            xf_n = __ldg(&d_XF[(size_t)(t + 1) * Hn + r0 + tid]);
            xh_n = __ldg(&d_XH[(size_t)(t + 1) * Hn + r0 + tid]);
        }

#pragma unroll
        for (int r = 0; r < MAXR; r++) {
            acc[r] = wr[r][0].x * gv0.x + wr[r][0].y * gv0.y
                   + wr[r][0].z * gv0.z + wr[r][0].w * gv0.w
                   + wr[r][1].x * gv1.x + wr[r][1].y * gv1.y
                   + wr[r][1].z * gv1.z + wr[r][1].w * gv1.w;
        }
#pragma unroll
        for (int p = 0; p < 7; p++) {
            float a = acc[2 * p], c = acc[2 * p + 1];
            a += __shfl_xor_sync(0xffffffffu, a, 16);
            c += __shfl_xor_sync(0xffffffffu, c, 16);
            float m = (lane < 16) ? a : c;
            m += __shfl_xor_sync(0xffffffffu, m, 8);
            m += __shfl_xor_sync(0xffffffffu, m, 4);
            m += __shfl_xor_sync(0xffffffffu, m, 2);
            m += __shfl_xor_sync(0xffffffffu, m, 1);
            if (lane == 0)       sPart[2 * p][wid]     = m;
            else if (lane == 16) sPart[2 * p + 1][wid] = m;
        }
        bar1();
        if (tid < nr) {
            float4 p0 = *(const float4 *)&sPart[tid][0];
            float4 p1 = *(const float4 *)&sPart[tid][4];
            float s = (p0.x + p0.y) + (p0.z + p0.w)
                    + (p1.x + p1.y) + (p1.z + p1.w);
            float z  = s + sBhf[tid] + xh_c;
            float e2 = __expf(2.f * z);
            float hh = 1.f - 2.f / (e2 + 1.f);      // tanh(z)
            float f  = sF[tid];
            float ho = sHold[tid];
            float hn = ho + f * (hh - ho);          // (1-f)*h + f*h_hat
            sHold[tid] = hn;
            int row = r0 + tid;
            out[(size_t)t * Hn + row] = hn;
            __stcg(&d_hbuf[row], hn);
            if (t == SEQ - 1) out[(size_t)SEQ * Hn + row] = hn;  // h_final
        }
        bar1();
        if (t < SEQ - 1) {
            if (tid == 0) red_arrive(&d_count);      // gen 2t+3
#pragma unroll
            for (int r = 0; r < MAXR; r++) {         // preload Wfh for next step
                wr[r][0] = *(const float4 *)(sWf + r * Hn + cA);
                wr[r][1] = *(const float4 *)(sWf + r * Hn + cB);
            }
            bar2();                                  // gen 2t+3 synced: h ready
        }
        xf_c = xf_n;
        xh_c = xh_n;
    }
}

// ------------------------------------------------------------------
extern "C" void kernel_launch(void* const* d_in, const int* in_sizes, int n_in,
                              void* d_out, int out_size)
{
    const float* x   = (const float *)d_in[0];
    const float* h0  = (const float *)d_in[1];
    const float* Wfx = (const float *)d_in[2];
    const float* bfx = (const float *)d_in[3];
    const float* Wfh = (const float *)d_in[4];
    const float* bfh = (const float *)d_in[5];
    const float* Whf = (const float *)d_in[6];
    const float* bhf = (const float *)d_in[7];
    const float* Whx = (const float *)d_in[8];
    const float* bhx = (const float *)d_in[9];
    float* out = (float *)d_out;

    (void)in_sizes; (void)n_in; (void)out_size;

    const size_t smem = (size_t)MAXR * Hn * 2 * sizeof(float);  // 229376 B
    cudaFuncSetAttribute(mgu_scan, cudaFuncAttributeMaxDynamicSharedMemorySize,
                         (int)smem);

    mgu_gemm<<<dim3(16, 16, 2), 256>>>(x, Wfx, bfx, Whx, bhx);
    mgu_scan<<<NBLK, TPB, smem>>>(h0, Wfh, bfh, Whf, bhf, out);
}